// round 2
// baseline (speedup 1.0000x reference)
#include <cuda_runtime.h>
#include <cstdint>
#include <cstdio>

// GraphSAGE: N nodes, D=64 features, L=3 layers, E edges.
//   deg[v]   = #incoming edges (dst==v);  inv[v] = 1/max(deg,1)
//   per layer: agg = scatter_add(x[src] -> dst) * inv
//              x   = relu(agg @ Wl[l]^T + bl[l] + x @ Wr[l]^T)
// Output: final x  [N, 64] fp32.

#define NODES_MAX 100000
#define DD 64
#define WPAD 68          // padded row stride (floats) for weight tiles in smem
#define NPAD 68          // padded row stride for input tiles in smem
#define UPD_SMEM ((2*64*WPAD + 2*128*NPAD) * 4)   // 104448 bytes

__device__ float g_agg [(size_t)NODES_MAX * DD];
__device__ float g_bufA[(size_t)NODES_MAX * DD];
__device__ float g_bufB[(size_t)NODES_MAX * DD];
__device__ float g_inv [NODES_MAX];
__device__ int   g_is64;

// ---------------------------------------------------------------------------
// Detect edge_index dtype: int64 values < N have zero high words.
// ---------------------------------------------------------------------------
__global__ void k_detect(const int* __restrict__ ei32) {
    int is64 = 1;
    #pragma unroll 1
    for (int i = 0; i < 64; ++i) {
        if (ei32[2 * i + 1] != 0) { is64 = 0; break; }
    }
    g_is64 = is64;
}

__device__ __forceinline__ int fetch_idx(const void* ei, long long pos, int is64) {
    if (is64) return (int)((const long long*)ei)[pos];
    return ((const int*)ei)[pos];
}

// ---------------------------------------------------------------------------
// Zero helpers (device-global scratch, so no pointers needed)
// ---------------------------------------------------------------------------
__global__ void k_zero_inv(int n) {
    int i = blockIdx.x * blockDim.x + threadIdx.x;
    if (i < n) g_inv[i] = 0.0f;
}

__global__ void k_zero_agg(int n) {          // n nodes -> n*16 float4
    int n4 = n * 16;
    float4 z = make_float4(0.f, 0.f, 0.f, 0.f);
    float4* p = (float4*)g_agg;
    for (int i = blockIdx.x * blockDim.x + threadIdx.x; i < n4;
         i += gridDim.x * blockDim.x)
        p[i] = z;
}

// ---------------------------------------------------------------------------
// Degree (counts into g_inv), then invert in-place
// ---------------------------------------------------------------------------
__global__ void k_deg(const void* __restrict__ ei, int E) {
    int e = blockIdx.x * blockDim.x + threadIdx.x;
    if (e >= E) return;
    int is64 = g_is64;
    int d = fetch_idx(ei, (long long)E + e, is64);
    atomicAdd(&g_inv[d], 1.0f);
}

__global__ void k_invert(int n) {
    int v = blockIdx.x * blockDim.x + threadIdx.x;
    if (v < n) g_inv[v] = 1.0f / fmaxf(g_inv[v], 1.0f);
}

// ---------------------------------------------------------------------------
// Scatter: agg[dst] += x[src].  16 lanes per edge, one float4 + one
// red.global.add.v4.f32 per lane (4x fewer atomic ops than scalar adds).
// ---------------------------------------------------------------------------
__global__ void k_scatter(const float4* __restrict__ x4,
                          const void* __restrict__ ei, int E) {
    long long t = (long long)blockIdx.x * blockDim.x + threadIdx.x;
    int c = (int)(t & 15);
    long long e = t >> 4;
    if (e >= (long long)E) return;
    int is64 = g_is64;
    int s = fetch_idx(ei, e, is64);
    int d = fetch_idx(ei, (long long)E + e, is64);
    float4 v = x4[(size_t)s * 16 + c];
    float* p = &g_agg[(size_t)d * 64 + c * 4];
    asm volatile("red.global.add.v4.f32 [%0], {%1,%2,%3,%4};"
                 :: "l"(p), "f"(v.x), "f"(v.y), "f"(v.z), "f"(v.w)
                 : "memory");
}

// ---------------------------------------------------------------------------
// Fused update: out = relu( (agg*inv) @ Wl^T + bl + x @ Wr^T )
// 256 threads / 128 nodes per block. Thread = 8 nodes x 4 output features.
// Weights (2x 64x64) + input tiles (2x 128x64) staged in padded smem.
// ---------------------------------------------------------------------------
__global__ void __launch_bounds__(256, 2)
k_update(const float* __restrict__ xin,
         const float* __restrict__ Wl, const float* __restrict__ bl,
         const float* __restrict__ Wr,
         float* __restrict__ xout, int n)
{
    extern __shared__ float smem[];
    float* sWl = smem;                    // [64][WPAD]
    float* sWr = sWl + 64 * WPAD;         // [64][WPAD]
    float* sA  = sWr + 64 * WPAD;         // [128][NPAD]
    float* sX  = sA  + 128 * NPAD;        // [128][NPAD]

    const int tid = threadIdx.x;

    // Stage weights (64x16 float4 each)
    for (int idx = tid; idx < 64 * 16; idx += 256) {
        int r = idx >> 4, c = idx & 15;
        float4 wl = ((const float4*)Wl)[idx];
        float4 wr = ((const float4*)Wr)[idx];
        *(float4*)(sWl + r * WPAD + c * 4) = wl;
        *(float4*)(sWr + r * WPAD + c * 4) = wr;
    }

    // Stage inputs: a = agg*inv, x
    const int base = blockIdx.x * 128;
    for (int idx = tid; idx < 128 * 16; idx += 256) {
        int v = idx >> 4, c = idx & 15;
        int vg = base + v;
        float4 a  = make_float4(0.f, 0.f, 0.f, 0.f);
        float4 xv = a;
        if (vg < n) {
            float iv = g_inv[vg];
            a  = *(const float4*)(g_agg + (size_t)vg * 64 + c * 4);
            xv = *(const float4*)(xin   + (size_t)vg * 64 + c * 4);
            a.x *= iv; a.y *= iv; a.z *= iv; a.w *= iv;
        }
        *(float4*)(sA + v * NPAD + c * 4) = a;
        *(float4*)(sX + v * NPAD + c * 4) = xv;
    }
    __syncthreads();

    const int ng = tid >> 4;   // 0..15, node group
    const int jg = tid & 15;   // 0..15, feature group

    float acc[8][4];
    #pragma unroll
    for (int i = 0; i < 8; ++i)
        #pragma unroll
        for (int jj = 0; jj < 4; ++jj) acc[i][jj] = 0.f;

    #pragma unroll 1
    for (int k4 = 0; k4 < 16; ++k4) {
        float4 wl[4], wr[4];
        #pragma unroll
        for (int jj = 0; jj < 4; ++jj) {
            int j = jj * 16 + jg;
            wl[jj] = *(const float4*)(sWl + j * WPAD + k4 * 4);
            wr[jj] = *(const float4*)(sWr + j * WPAD + k4 * 4);
        }
        #pragma unroll
        for (int i = 0; i < 8; ++i) {
            int v = i * 16 + ng;
            float4 a  = *(const float4*)(sA + v * NPAD + k4 * 4);
            float4 xv = *(const float4*)(sX + v * NPAD + k4 * 4);
            #pragma unroll
            for (int jj = 0; jj < 4; ++jj) {
                acc[i][jj] += a.x  * wl[jj].x + a.y  * wl[jj].y
                            + a.z  * wl[jj].z + a.w  * wl[jj].w
                            + xv.x * wr[jj].x + xv.y * wr[jj].y
                            + xv.z * wr[jj].z + xv.w * wr[jj].w;
            }
        }
    }

    float bias[4];
    #pragma unroll
    for (int jj = 0; jj < 4; ++jj) bias[jj] = bl[jj * 16 + jg];

    #pragma unroll
    for (int i = 0; i < 8; ++i) {
        int vg = base + i * 16 + ng;
        if (vg < n) {
            #pragma unroll
            for (int jj = 0; jj < 4; ++jj) {
                int j = jj * 16 + jg;
                xout[(size_t)vg * 64 + j] = fmaxf(acc[i][jj] + bias[jj], 0.f);
            }
        }
    }
}

// ---------------------------------------------------------------------------
// Launcher
// ---------------------------------------------------------------------------
extern "C" void kernel_launch(void* const* d_in, const int* in_sizes, int n_in,
                              void* d_out, int out_size)
{
    const float* x  = (const float*)d_in[0];
    const float* Wl = (const float*)d_in[1];
    const float* bl = (const float*)d_in[2];
    const float* Wr = (const float*)d_in[3];
    const void*  ei = d_in[4];

    const int n = in_sizes[0] / DD;         // 100000
    const int E = in_sizes[4] / 2;          // 1600000
    const int L = in_sizes[1] / (DD * DD);  // 3

    float *bufA = nullptr, *bufB = nullptr;
    cudaGetSymbolAddress((void**)&bufA, g_bufA);
    cudaGetSymbolAddress((void**)&bufB, g_bufB);

    cudaFuncSetAttribute(k_update, cudaFuncAttributeMaxDynamicSharedMemorySize,
                         UPD_SMEM);

    // dtype detection + degree + inverse
    k_detect<<<1, 1>>>((const int*)ei);
    k_zero_inv<<<(n + 255) / 256, 256>>>(n);
    k_deg<<<(E + 255) / 256, 256>>>(ei, E);
    k_invert<<<(n + 255) / 256, 256>>>(n);

    const float* cur = x;
    for (int l = 0; l < L; ++l) {
        k_zero_agg<<<4096, 256>>>(n);

        long long sthreads = (long long)E * 16;
        int sblocks = (int)((sthreads + 255) / 256);
        k_scatter<<<sblocks, 256>>>((const float4*)cur, ei, E);

        float* outp = (l == L - 1) ? (float*)d_out
                                   : ((l & 1) ? bufB : bufA);
        k_update<<<(n + 127) / 128, 256, UPD_SMEM>>>(
            cur, Wl + (size_t)l * DD * DD, bl + (size_t)l * DD,
            Wr + (size_t)l * DD * DD, outp, n);
        cur = outp;
    }
}